// round 17
// baseline (speedup 1.0000x reference)
#include <cuda_runtime.h>
#include <cuda_fp16.h>
#include <stdint.h>
#include <math.h>

#define B_SZ 2048
#define T_SZ 512
#define D_IN 64
#define H    128
#define D_OUT 64
#define NB   16
#define NTH  256
#define NSTEPS (T_SZ-1)
#define ROWB 272   // activation buffer row stride in bytes (128 fp16 + 16B pad)

// SMEM byte offsets (single-fp16 weight frags: 32KB each)
#define SM_WF1 0        // W1 fragments (32KB, uint2 {b0,b1} fp16)
#define SM_WFP 32768    // P fragments
#define SM_WFQ 65536    // Q fragments
#define SM_AB0 98304    // activation ping  [16][ROWB] fp16 (4352B)
#define SM_AB1 102656   // activation pong
#define SM_XS  107008   // 16 floats
#define SMEM_BYTES 107072

__device__ float g_P[H * H];               // P = W1 @ W2   (row-major [j][k])
__device__ float g_Q[H * H];               // Q = Whh @ W2  (row-major [j][k])
__device__ unsigned long long g_W2f[4096]; // W2 fragments (32KB, uint2 layout)
__device__ unsigned long long g_Whf[4096]; // Whh fragments (32KB, uint2 layout)

__device__ __forceinline__ uint32_t smem_u32(const void* p) {
    uint32_t a;
    asm("{ .reg .u64 t; cvta.to.shared.u64 t, %1; cvt.u32.u64 %0, t; }" : "=r"(a) : "l"(p));
    return a;
}
__device__ __forceinline__ uint32_t pk2h(float a, float b) {
    __half2 h = __floats2half2_rn(a, b);
    return *(uint32_t*)&h;
}
__device__ __forceinline__ void ldsm4(uint32_t& r0, uint32_t& r1, uint32_t& r2,
                                      uint32_t& r3, uint32_t addr) {
    asm volatile("ldmatrix.sync.aligned.m8n8.x4.shared.b16 {%0,%1,%2,%3}, [%4];"
                 : "=r"(r0), "=r"(r1), "=r"(r2), "=r"(r3) : "r"(addr));
}
__device__ __forceinline__ void mma_f16(float* d, uint32_t a0, uint32_t a1,
                                        uint32_t a2, uint32_t a3,
                                        uint32_t b0, uint32_t b1) {
    asm volatile("mma.sync.aligned.m16n8k16.row.col.f32.f16.f16.f32 "
                 "{%0,%1,%2,%3}, {%4,%5,%6,%7}, {%8,%9}, {%0,%1,%2,%3};"
                 : "+f"(d[0]), "+f"(d[1]), "+f"(d[2]), "+f"(d[3])
                 : "r"(a0), "r"(a1), "r"(a2), "r"(a3), "r"(b0), "r"(b1));
}
__device__ __forceinline__ float tanh_hw(float v) {
    float t;
    asm("tanh.approx.f32 %0, %1;" : "=f"(t) : "f"(v));
    return t;
}
__device__ __forceinline__ float silu_f(float v) {
    const float hv = 0.5f * v;
    return fmaf(hv, tanh_hw(hv), hv);
}

// Stage 8 fragment values as single fp16 (4 STS.32 per thread).
__device__ __forceinline__ void stage8(char* ab, const float* v,
                                       uint32_t o00, uint32_t o10) {
#pragma unroll
    for (int ntl = 0; ntl < 2; ntl++) {
        *(uint32_t*)(ab + o00 + ntl*16) = pk2h(v[ntl*4+0], v[ntl*4+1]);
        *(uint32_t*)(ab + o10 + ntl*16) = pk2h(v[ntl*4+2], v[ntl*4+3]);
    }
}

// Weight fragment uint2 layout: addr = ntile*2048 + s*256 + lane*8 ; v = {b0, b1}

// GEMM, weights from SMEM: k-split into 2 acc groups -> 4 chains of depth 4.
__device__ __forceinline__ void gemm16s(uint32_t ab_u32, uint32_t aoff,
                                        const char* wf, uint32_t boff,
                                        float* dout) {
    float a0[8], a1[8];
#pragma unroll
    for (int i = 0; i < 8; i++) { a0[i] = 0.f; a1[i] = 0.f; }
#pragma unroll
    for (int s = 0; s < 8; s++) {
        float* acc = (s < 4) ? a0 : a1;
        uint32_t ah0, ah1, ah2, ah3;
        ldsm4(ah0, ah1, ah2, ah3, ab_u32 + aoff + s*32);
#pragma unroll
        for (int ntl = 0; ntl < 2; ntl++) {
            const uint2 b = *(const uint2*)(wf + boff + ntl*2048 + s*256);
            mma_f16(acc + ntl*4, ah0, ah1, ah2, ah3, b.x, b.y);
        }
    }
#pragma unroll
    for (int i = 0; i < 8; i++) dout[i] = a0[i] + a1[i];
}

// GEMM, weights from persistent registers (P matrix), k-split chains.
__device__ __forceinline__ void gemm16r(uint32_t ab_u32, uint32_t aoff,
                                        const uint2* PB, float* dout) {
    float a0[8], a1[8];
#pragma unroll
    for (int i = 0; i < 8; i++) { a0[i] = 0.f; a1[i] = 0.f; }
#pragma unroll
    for (int s = 0; s < 8; s++) {
        float* acc = (s < 4) ? a0 : a1;
        uint32_t ah0, ah1, ah2, ah3;
        ldsm4(ah0, ah1, ah2, ah3, ab_u32 + aoff + s*32);
#pragma unroll
        for (int ntl = 0; ntl < 2; ntl++) {
            const uint2 b = PB[s*2 + ntl];
            mma_f16(acc + ntl*4, ah0, ah1, ah2, ah3, b.x, b.y);
        }
    }
#pragma unroll
    for (int i = 0; i < 8; i++) dout[i] = a0[i] + a1[i];
}

// GEMM, weights streamed from global (L2), prefetched; k-split chains.
__device__ __forceinline__ void gemm16g(uint32_t ab_u32, uint32_t aoff,
                                        const char* gw, uint32_t boff,
                                        float* dout) {
    uint2 B[16];
#pragma unroll
    for (int s = 0; s < 8; s++)
#pragma unroll
        for (int ntl = 0; ntl < 2; ntl++)
            B[s*2+ntl] = __ldg((const uint2*)(gw + boff + ntl*2048 + s*256));
    float a0[8], a1[8];
#pragma unroll
    for (int i = 0; i < 8; i++) { a0[i] = 0.f; a1[i] = 0.f; }
#pragma unroll
    for (int s = 0; s < 8; s++) {
        float* acc = (s < 4) ? a0 : a1;
        uint32_t ah0, ah1, ah2, ah3;
        ldsm4(ah0, ah1, ah2, ah3, ab_u32 + aoff + s*32);
#pragma unroll
        for (int ntl = 0; ntl < 2; ntl++) {
            const uint2 b = B[s*2+ntl];
            mma_f16(acc + ntl*4, ah0, ah1, ah2, ah3, b.x, b.y);
        }
    }
#pragma unroll
    for (int i = 0; i < 8; i++) dout[i] = a0[i] + a1[i];
}

// L1 dual GEMM: W1 (SMEM) -> zout and Whh (pre-fetched regs WH) -> swout.
// k-split -> 8 chains of depth 4.
__device__ __forceinline__ void gemm_dual(uint32_t ab_u32, uint32_t aoff,
                                          const char* wf1, const uint2* WH,
                                          uint32_t boff,
                                          float* zout, float* swout) {
    float z0[8], z1a[8], s0[8], s1[8];
#pragma unroll
    for (int i = 0; i < 8; i++) { z0[i] = 0.f; z1a[i] = 0.f; s0[i] = 0.f; s1[i] = 0.f; }
#pragma unroll
    for (int s = 0; s < 8; s++) {
        float* zacc = (s < 4) ? z0 : z1a;
        float* sacc = (s < 4) ? s0 : s1;
        uint32_t ah0, ah1, ah2, ah3;
        ldsm4(ah0, ah1, ah2, ah3, ab_u32 + aoff + s*32);
#pragma unroll
        for (int ntl = 0; ntl < 2; ntl++) {
            const uint2 b = *(const uint2*)(wf1 + boff + ntl*2048 + s*256);
            const uint2 w = WH[s*2 + ntl];
            mma_f16(zacc + ntl*4, ah0, ah1, ah2, ah3, b.x, b.y);
            mma_f16(sacc + ntl*4, ah0, ah1, ah2, ah3, w.x, w.y);
        }
    }
#pragma unroll
    for (int i = 0; i < 8; i++) {
        zout[i]  = z0[i] + z1a[i];
        swout[i] = s0[i] + s1[i];
    }
}

// ---- prep kernels ----
__global__ void prep_mm(const float* __restrict__ A, const float* __restrict__ B,
                        int sel) {
    __shared__ float arow[H];
    const int j = blockIdx.x, k = threadIdx.x;
    arow[k] = A[j * H + k];
    __syncthreads();
    float s = 0.0f;
#pragma unroll 8
    for (int m = 0; m < H; m++) s = fmaf(arow[m], B[m * H + k], s);
    (sel ? g_Q : g_P)[j * H + k] = s;
}

__global__ void prep_frag(const float* __restrict__ W, int sel) {
    const int fi = blockIdx.x * blockDim.x + threadIdx.x;  // 0..4095
    const int ntile = fi >> 8, s = (fi >> 5) & 7, ln = fi & 31;
    const int n = ntile * 8 + (ln >> 2);
    const int k0 = s * 16 + 2 * (ln & 3);
    uint2 v;
    v.x = pk2h(W[n*H + k0],     W[n*H + k0 + 1]);
    v.y = pk2h(W[n*H + k0 + 8], W[n*H + k0 + 9]);
    char* base = (char*)(sel ? g_Whf : g_W2f) + ntile*2048 + s*256 + ln*8;
    *(uint2*)base = v;
}

__global__ void __launch_bounds__(NTH, 1)
rnnode_mma(const float* __restrict__ x, const float* __restrict__ span,
           const float* __restrict__ W_emb, const float* __restrict__ b_emb,
           const float* __restrict__ W_ih, const float* __restrict__ b_ih,
           const float* __restrict__ W_hh, const float* __restrict__ b_hh,
           const float* __restrict__ W1, const float* __restrict__ b1,
           const float* __restrict__ W2, const float* __restrict__ b2,
           const float* __restrict__ W_out, const float* __restrict__ b_out,
           float* __restrict__ out) {
    extern __shared__ char smc[];
    const uint32_t smb = smem_u32(smc);
    const int tid = threadIdx.x;
    const int lane = tid & 31, wid = tid >> 5;
    const int bb0 = blockIdx.x * NB;
    float* xs = (float*)(smc + SM_XS);

    // ---- fill SMEM weight fragment buffers (W1, P, Q), uint2 fp16 layout ----
#pragma unroll 1
    for (int m = 0; m < 3; m++) {
        const float* W = (m == 0) ? W1 : (m == 1) ? g_P : g_Q;
        char* wf = smc + (m == 0 ? SM_WF1 : m == 1 ? SM_WFP : SM_WFQ);
        for (int fi = tid; fi < 4096; fi += NTH) {
            const int ntile = fi >> 8, s = (fi >> 5) & 7, ln = fi & 31;
            const int n = ntile * 8 + (ln >> 2);
            const int k0 = s * 16 + 2 * (ln & 3);
            uint2 v;
            v.x = pk2h(W[n*H + k0],     W[n*H + k0 + 1]);
            v.y = pk2h(W[n*H + k0 + 8], W[n*H + k0 + 9]);
            *(uint2*)(wf + ntile*2048 + s*256 + ln*8) = v;
        }
    }

    // ---- per-thread fragment geometry ----
    const int g0 = lane >> 2, tq = lane & 3;
    const int r0 = g0, r1 = g0 + 8;
    const int cb0 = wid * 16 + 2 * tq;
    const uint32_t o00 = (uint32_t)(r0 * ROWB + cb0 * 2);
    const uint32_t o10 = (uint32_t)(r1 * ROWB + cb0 * 2);
    const uint32_t arow = (uint32_t)((((lane >> 3) & 1) * 8) + (lane & 7));
    const uint32_t aoff = arow * ROWB + (((lane >> 4) & 1) * 16);
    const uint32_t boff = (uint32_t)((wid * 2) * 2048 + lane * 8);

    // ---- per-col constants for cols {cb0, cb0+1, cb0+8, cb0+9} ----
    float cv[4], ccst[4], b1c[4], b2c[4], c1c[4], cwc[4];
#pragma unroll
    for (int q = 0; q < 4; q++) {
        const int col = cb0 + (q >> 1) * 8 + (q & 1);
        float vv = 0.0f, cc = 0.0f;
        for (int d = 0; d < D_IN; d++) {
            const float w = W_ih[col * D_IN + d];
            vv = fmaf(w, W_emb[d], vv);
            cc = fmaf(w, b_emb[d], cc);
        }
        cv[q] = vv;
        ccst[q] = cc + b_ih[col] + b_hh[col];
        b1c[q] = b1[col];
        b2c[q] = b2[col];
        float c1v = 0.0f, cwv = 0.0f;
        for (int k = 0; k < H; k++) {
            c1v = fmaf(b2[k], W1[col * H + k], c1v);
            cwv = fmaf(b2[k], W_hh[col * H + k], cwv);
        }
        c1c[q] = c1v;   // b2 @ W1^T
        cwc[q] = cwv;   // b2 @ Whh^T
    }
    if (tid < NB) xs[tid] = x[(size_t)(bb0 + tid) * T_SZ];
    __syncthreads();

    const uint32_t abu[2] = {smb + SM_AB0, smb + SM_AB1};
    char* abp[2] = {smc + SM_AB0, smc + SM_AB1};
    const char* wf1 = smc + SM_WF1;
    const char* wfq = smc + SM_WFQ;
    const char* gw2 = (const char*)g_W2f;
    const char* gwh = (const char*)g_Whf;

    // ---- persistent P fragments (16 uint2 = 32 regs) ----
    uint2 PB[16];
    {
        const char* wfp = smc + SM_WFP;
#pragma unroll
        for (int idx = 0; idx < 16; idx++) {
            const int s = idx >> 1, ntl = idx & 1;
            PB[idx] = *(const uint2*)(wfp + boff + ntl*2048 + s*256);
        }
    }

#define QSEL(i) (((i) >> 2) * 2 + ((i) & 1))
#define RSEL(i) ((((i) >> 1) & 1))

    // htan_0 = tanh(x_0*v + c)   (s_0 = 0 since h_0 = 0)
    float htan[8], sW[8], z1[8], u1[8], u2[8], u3[8], g[8];
    {
        const float xr[2] = {xs[r0], xs[r1]};
#pragma unroll
        for (int i = 0; i < 8; i++) {
            const int q = QSEL(i);
            htan[i] = tanh_hw(fmaf(xr[RSEL(i)], cv[q], ccst[q]));
        }
    }
    int p = 0;
    float dtL = 1.0f;

#pragma unroll 1
    for (int t = 0; t < NSTEPS; t++) {
        const float dt   = __ldg(span + t + 1) - __ldg(span + t);
        const float dt3  = dt * (1.0f / 3.0f);
        const float dt23 = 2.0f * dt3;
        const float dt8  = dt * 0.125f;
        dtL = dt;

        // Prefetch Whh frags (independent of staging -> L2 latency hides
        // under stage + barrier).
        uint2 WH[16];
#pragma unroll
        for (int idx = 0; idx < 16; idx++) {
            const int s = idx >> 1, ntl = idx & 1;
            WH[idx] = __ldg((const uint2*)(gwh + boff + ntl*2048 + s*256));
        }

        // L1: stage htan; dual GEMM: W1 (SMEM) -> z1, Whh (regs) -> sW
        stage8(abp[p], htan, o00, o10);
        if (tid < NB) xs[tid] = x[(size_t)(bb0 + tid) * T_SZ + (t + 1)];
        __syncthreads();
        gemm_dual(abu[p], aoff, wf1, WH, boff, g, sW);
        p ^= 1;
#pragma unroll
        for (int i = 0; i < 8; i++) {
            z1[i] = g[i] + b1c[QSEL(i)];
            u1[i] = silu_f(z1[i]);
        }
        // L2: u2 = silu(z1 + dt/3*(u1@P^T + c1))
        stage8(abp[p], u1, o00, o10);
        __syncthreads();
        gemm16r(abu[p], aoff, PB, g);
        p ^= 1;
#pragma unroll
        for (int i = 0; i < 8; i++) {
            u2[i] = silu_f(fmaf(dt3, g[i] + c1c[QSEL(i)], z1[i]));
            g[i] = fmaf(-(1.0f / 3.0f), u1[i], u2[i]);
        }
        // L3: u3 = silu(z1 + dt*((u2-u1/3)@P^T) + 2dt/3*c1)
        stage8(abp[p], g, o00, o10);
        __syncthreads();
        gemm16r(abu[p], aoff, PB, g);
        p ^= 1;
#pragma unroll
        for (int i = 0; i < 8; i++) {
            u3[i] = silu_f(fmaf(dt, g[i], fmaf(dt23, c1c[QSEL(i)], z1[i])));
            g[i] = u1[i] - u2[i] + u3[i];
        }
        // L4: u4 = silu(z1 + dt*((u1-u2+u3)@P^T + c1)); g4 = u1+3(u2+u3)+u4
        stage8(abp[p], g, o00, o10);
        __syncthreads();
        gemm16r(abu[p], aoff, PB, g);
        p ^= 1;
#pragma unroll
        for (int i = 0; i < 8; i++) {
            const float u4 = silu_f(fmaf(dt, g[i] + c1c[QSEL(i)], z1[i]));
            g[i] = fmaf(3.0f, u2[i] + u3[i], u1[i] + u4);
        }
        // L5 (skip on last step): s+ = sW + dt/8*(g4@Q^T) + dt*cw ;
        //                         htan+ = tanh(x+*v + c + s+)
        stage8(abp[p], g, o00, o10);
        __syncthreads();
        if (t + 1 < NSTEPS) {
            gemm16s(abu[p], aoff, wfq, boff, g);
            p ^= 1;
            const float xr[2] = {xs[r0], xs[r1]};
#pragma unroll
            for (int i = 0; i < 8; i++) {
                const int q = QSEL(i);
                const float s = fmaf(dt8, g[i], fmaf(dt, cwc[q], sW[i]));
                htan[i] = tanh_hw(fmaf(xr[RSEL(i)], cv[q], ccst[q]) + s);
            }
        }
    }

    // ---- final h = htan + dt/8*(g4@W2^T) + dt*b2 (g4 staged in buf p) ----
    {
        gemm16g(abu[p], aoff, gw2, boff, g);
        const float dt8L = dtL * 0.125f;
#pragma unroll
        for (int i = 0; i < 8; i++)
            htan[i] = fmaf(dt8L, g[i], fmaf(dtL, b2c[QSEL(i)], htan[i]));
    }

    // ---- epilogue: out = h @ W_out^T + b_out ----
    __syncthreads();
    float* hb = (float*)smc;  // reuse WF1 region: [16][128] fp32
#pragma unroll
    for (int ntl = 0; ntl < 2; ntl++) {
        const int c = cb0 + ntl * 8;
        hb[r0 * H + c]     = htan[ntl*4+0];
        hb[r0 * H + c + 1] = htan[ntl*4+1];
        hb[r1 * H + c]     = htan[ntl*4+2];
        hb[r1 * H + c + 1] = htan[ntl*4+3];
    }
    __syncthreads();
    {
        const int j = tid & 63, q = tid >> 6;
        float o[4];
        const float bo = __ldg(b_out + j);
#pragma unroll
        for (int n = 0; n < 4; n++) o[n] = bo;
        const float* Wo = W_out + j * H;
#pragma unroll 4
        for (int k = 0; k < H; k++) {
            const float wv = __ldg(Wo + k);
            const float* ar = hb + (q * 4) * H + k;
#pragma unroll
            for (int n = 0; n < 4; n++) o[n] = fmaf(ar[n * H], wv, o[n]);
        }
#pragma unroll
        for (int n = 0; n < 4; n++)
            out[(size_t)(bb0 + q * 4 + n) * D_OUT + j] = o[n];
    }
}

extern "C" void kernel_launch(void* const* d_in, const int* in_sizes, int n_in,
                              void* d_out, int out_size) {
    const float* x     = (const float*)d_in[0];
    const float* span  = (const float*)d_in[1];
    const float* W_emb = (const float*)d_in[2];
    const float* b_emb = (const float*)d_in[3];
    const float* W_ih  = (const float*)d_in[4];
    const float* b_ih  = (const float*)d_in[5];
    const float* W_hh  = (const float*)d_in[6];
    const float* b_hh  = (const float*)d_in[7];
    const float* W1    = (const float*)d_in[8];
    const float* b1    = (const float*)d_in[9];
    const float* W2    = (const float*)d_in[10];
    const float* b2    = (const float*)d_in[11];
    const float* W_out = (const float*)d_in[12];
    const float* b_out = (const float*)d_in[13];
    float* out = (float*)d_out;

    prep_mm<<<H, H>>>(W1, W2, 0);     // P = W1 @ W2
    prep_mm<<<H, H>>>(W_hh, W2, 1);   // Q = Whh @ W2
    prep_frag<<<16, 256>>>(W2, 0);
    prep_frag<<<16, 256>>>(W_hh, 1);
    cudaFuncSetAttribute(rnnode_mma, cudaFuncAttributeMaxDynamicSharedMemorySize,
                         SMEM_BYTES);
    rnnode_mma<<<B_SZ / NB, NTH, SMEM_BYTES>>>(
        x, span, W_emb, b_emb, W_ih, b_ih, W_hh, b_hh,
        W1, b1, W2, b2, W_out, b_out, out);
}